// round 12
// baseline (speedup 1.0000x reference)
#include <cuda_runtime.h>
#include <math.h>

#define TT 48
#define SS 1024
#define HS 512
#define BB 256
#define TAG_START 45
#define TAG_STOP  46

typedef unsigned long long u64;

// scratch (device globals: allocation-free; zero-initialized at load)
__device__ float    g_vec[2][BB][64];   // [0]=alpha (fwd), [1]=gamma (bwd)
__device__ int      g_eac[2][BB];
__device__ float    g_gold[BB];
__device__ unsigned g_cnt[BB];          // last-finisher counters (reset after use)

// ---- packed f32x2 helpers ----
__device__ __forceinline__ u64 ffma2(u64 a, u64 b, u64 c){
    u64 d; asm("fma.rn.f32x2 %0, %1, %2, %3;" : "=l"(d) : "l"(a), "l"(b), "l"(c)); return d;
}
__device__ __forceinline__ u64 fadd2(u64 a, u64 b){
    u64 d; asm("add.rn.f32x2 %0, %1, %2;" : "=l"(d) : "l"(a), "l"(b)); return d;
}
__device__ __forceinline__ u64 pack2(float lo, float hi){
    u64 d; asm("mov.b64 %0, {%1, %2};" : "=l"(d) : "f"(lo), "f"(hi)); return d;
}
__device__ __forceinline__ void unpack2(u64 v, float& lo, float& hi){
    asm("mov.b64 {%0, %1}, %2;" : "=f"(lo), "=f"(hi) : "l"(v));
}
__device__ __forceinline__ float2 expf2(float2 f){
    return make_float2(__expf(f.x), __expf(f.y));
}
__device__ __forceinline__ float2 ldf2(const float* p, bool act){
    return act ? *(const float2*)p : make_float2(0.f, 0.f);
}

// matvec via warp shuffles: lane k<24 exposes xmy=(p[2k],p[2k+1]).
// Produces s0,s1 (rows j0,j1) and p00 = p[0] (for renorm).
#define MATVEC_SH                                                             \
    u64 A0=0ull, A1=0ull, C0=0ull, C1=0ull;                                   \
    float p00 = 0.f;                                                          \
    _Pragma("unroll")                                                         \
    for (int q = 0; q < 12; q++){                                             \
        float ax = __shfl_sync(0xffffffffu, xmy.x, 2*q);                      \
        float ay = __shfl_sync(0xffffffffu, xmy.y, 2*q);                      \
        float bx = __shfl_sync(0xffffffffu, xmy.x, 2*q+1);                    \
        float by = __shfl_sync(0xffffffffu, xmy.y, 2*q+1);                    \
        if (q == 0) p00 = ax;                                                 \
        u64 Px = pack2(ax, ay), Py = pack2(bx, by);                           \
        A0 = ffma2(W0[2*q],   Px, A0);                                        \
        A1 = ffma2(W1[2*q],   Px, A1);                                        \
        C0 = ffma2(W0[2*q+1], Py, C0);                                        \
        C1 = ffma2(W1[2*q+1], Py, C1);                                        \
    }                                                                         \
    u64 S0 = fadd2(A0, C0), S1 = fadd2(A1, C1);                               \
    float l0, h0, l1, h1; unpack2(S0, l0, h0); unpack2(S1, l1, h1);           \
    float s0 = l0 + h0, s1 = l1 + h1;

// exact pow2 renorm factor from p[0] (exponent only, integer-exact)
#define RENORM                                                                \
    int e = ((__float_as_int(p00) >> 23) & 0xff) - 127;                       \
    e = max(-60, min(60, e));                                                 \
    float c = __int_as_float((127 - e) << 23);                                \
    eacc += e;

// forward steps (xmy == vmy)
#define FSTEP_R(EV, M) do { MATVEC_SH RENORM                                  \
    float qx = s0 * ((EV).x * c), qy = s1 * ((EV).y * c);                     \
    vmy.x = ((M) > 0.5f) ? qx : vmy.x * c;                                    \
    vmy.y = ((M) > 0.5f) ? qy : vmy.y * c;                                    \
    xmy = vmy;                                                                \
} while(0)

#define FSTEP_P(EV, M) do { MATVEC_SH                                         \
    float qx = s0 * (EV).x, qy = s1 * (EV).y;                                 \
    vmy.x = ((M) > 0.5f) ? qx : vmy.x;                                        \
    vmy.y = ((M) > 0.5f) ? qy : vmy.y;                                        \
    xmy = vmy;                                                                \
} while(0)

// backward steps (xmy == vmy * E_next, the speculative-E exchange value)
#define BSTEP_R(EN, M) do { MATVEC_SH RENORM                                  \
    float qx = s0 * c, qy = s1 * c;                                           \
    vmy.x = ((M) > 0.5f) ? qx : vmy.x * c;                                    \
    vmy.y = ((M) > 0.5f) ? qy : vmy.y * c;                                    \
    xmy = make_float2(vmy.x*(EN).x, vmy.y*(EN).y);                            \
} while(0)

#define BSTEP_P(EN, M) do { MATVEC_SH                                         \
    vmy.x = ((M) > 0.5f) ? s0 : vmy.x;                                        \
    vmy.y = ((M) > 0.5f) ? s1 : vmy.y;                                        \
    xmy = make_float2(vmy.x*(EN).x, vmy.y*(EN).y);                            \
} while(0)

__global__ void __launch_bounds__(32) crf_scan_kernel(
    const float* __restrict__ feats,
    const float* __restrict__ masks,
    const void*  __restrict__ tagsp,
    const float* __restrict__ trans,
    float*       __restrict__ out)
{
    const int lane = threadIdx.x;
    const int b    = blockIdx.x;
    const int dir  = blockIdx.y;
    const int j0   = 2*lane;
    const bool act = (lane < 24);
    const float* fB = feats + (size_t)b * SS * TT;
    const float* mB = masks + (size_t)b * SS;

    if (dir == 2){
        // ---------------- gold-score block ----------------
        const int* t32 = (const int*)tagsp;
        int det = t32[1]|t32[3]|t32[5]|t32[7]|t32[9]|t32[11]|t32[13]|t32[15];
        const bool is64 = (det == 0);
        const long long* t64 = (const long long*)tagsp;

        float g = 0.f, lenf = 0.f;
        for (int si = lane; si < SS; si += 32){
            float m = mB[si];
            long long base = (long long)b * SS + si;
            int tg = is64 ? (int)t64[base] : t32[base];
            int pv = (si == 0) ? TAG_START : (is64 ? (int)t64[base-1] : t32[base-1]);
            g    += (fB[si*TT + tg] + trans[tg*TT + pv]) * m;
            lenf += m;
        }
        #pragma unroll
        for (int o = 16; o; o >>= 1){
            g    += __shfl_xor_sync(0xffffffffu, g,    o);
            lenf += __shfl_xor_sync(0xffffffffu, lenf, o);
        }
        if (lane == 0){
            int len = (int)lenf;
            int last = (len == 0) ? TAG_START
                                  : (is64 ? (int)t64[(long long)b*SS + len - 1]
                                          : t32[(long long)b*SS + len - 1]);
            g_gold[b] = g + trans[TAG_STOP*TT + last];
        }
    } else {
        // ---------------- scan block (dir 0 = fwd, 1 = bwd) ----------------
        u64 W0[24], W1[24];
        #pragma unroll
        for (int kk = 0; kk < 24; kk++){
            float a0=0.f, a1=0.f, c0=0.f, c1=0.f;
            if (act){
                if (dir == 0){
                    float2 t0 = *(const float2*)&trans[j0*TT + 2*kk];
                    float2 t1 = *(const float2*)&trans[(j0+1)*TT + 2*kk];
                    a0 = __expf(t0.x); a1 = __expf(t0.y);
                    c0 = __expf(t1.x); c1 = __expf(t1.y);
                } else {
                    a0 = __expf(trans[(2*kk  )*TT + j0]);
                    a1 = __expf(trans[(2*kk+1)*TT + j0]);
                    c0 = __expf(trans[(2*kk  )*TT + j0+1]);
                    c1 = __expf(trans[(2*kk+1)*TT + j0+1]);
                }
            }
            W0[kk] = pack2(a0, a1);
            W1[kk] = pack2(c0, c1);
        }

        float2 vmy, xmy;
        int eacc = 0;
        if (dir == 0){
            vmy.x = (j0   == TAG_START) ? 1.f : 0.f;
            vmy.y = (j0+1 == TAG_START) ? 1.f : 0.f;
            xmy = vmy;
        } else {
            float w0 = act ? __expf(trans[TAG_STOP*TT + j0  ]) : 0.f;
            float w1 = act ? __expf(trans[TAG_STOP*TT + j0+1]) : 0.f;
            vmy = make_float2(w0, w1);
            float2 eL = expf2(ldf2(&fB[(size_t)1023*TT + j0], act));
            xmy = make_float2(w0*eL.x, w1*eL.y);
        }

        // pipeline: raw loads 8 steps ahead, exp computed 4 steps ahead
        float2 e0[4], e1x[4], r1[4], r2[4];
        float4 m0, m1;

        if (dir == 0){
            #pragma unroll
            for (int u = 0; u < 4; u++){
                e0[u] = expf2(ldf2(&fB[(size_t)u*TT + j0], act));
                r1[u] = ldf2(&fB[(size_t)(4+u)*TT + j0], act);
            }
            m0 = *(const float4*)&mB[0];
            m1 = *(const float4*)&mB[4];

            for (int sb = 0; sb < HS; sb += 8){
                float4 m2 = *(const float4*)&mB[sb+8];
                #pragma unroll
                for (int u = 0; u < 4; u++){
                    r2[u]  = ldf2(&fB[(size_t)(sb+8+u)*TT + j0], act);
                    e1x[u] = expf2(r1[u]);
                }
                FSTEP_R(e0[0], m0.x); FSTEP_P(e0[1], m0.y);
                FSTEP_R(e0[2], m0.z); FSTEP_P(e0[3], m0.w);
                m0 = m2;

                float4 m1o = m1;
                m1 = *(const float4*)&mB[sb+12];
                #pragma unroll
                for (int u = 0; u < 4; u++){
                    r1[u] = ldf2(&fB[(size_t)(sb+12+u)*TT + j0], act);
                    e0[u] = expf2(r2[u]);
                }
                FSTEP_R(e1x[0], m1o.x); FSTEP_P(e1x[1], m1o.y);
                FSTEP_R(e1x[2], m1o.z); FSTEP_P(e1x[3], m1o.w);
            }
        } else {
            #pragma unroll
            for (int u = 0; u < 4; u++){
                e0[u] = expf2(ldf2(&fB[(size_t)(1022-u)*TT + j0], act));
                r1[u] = ldf2(&fB[(size_t)(1022-(4+u))*TT + j0], act);
            }
            m0 = *(const float4*)&mB[1020];   // reversed components
            m1 = *(const float4*)&mB[1016];

            for (int sb = 0; sb < HS; sb += 8){
                float4 m2 = *(const float4*)&mB[1020 - (sb+8)];
                #pragma unroll
                for (int u = 0; u < 4; u++){
                    r2[u]  = ldf2(&fB[(size_t)(1022-(sb+8+u))*TT + j0], act);
                    e1x[u] = expf2(r1[u]);
                }
                BSTEP_R(e0[0], m0.w); BSTEP_P(e0[1], m0.z);
                BSTEP_R(e0[2], m0.y); BSTEP_P(e0[3], m0.x);
                m0 = m2;

                float4 m1o = m1;
                m1 = *(const float4*)&mB[1020 - (sb+12)];
                #pragma unroll
                for (int u = 0; u < 4; u++){
                    r1[u] = ldf2(&fB[(size_t)(1022-(sb+12+u))*TT + j0], act);
                    e0[u] = expf2(r2[u]);
                }
                BSTEP_R(e1x[0], m1o.w); BSTEP_P(e1x[1], m1o.z);
                BSTEP_R(e1x[2], m1o.y); BSTEP_P(e1x[3], m1o.x);
            }
        }

        if (act){
            *(float2*)&g_vec[dir][b][j0] = vmy;
        } else {
            g_vec[dir][b][2*lane] = 0.f; g_vec[dir][b][2*lane+1] = 0.f;
        }
        if (lane == 0) g_eac[dir][b] = eacc;
    }

    // -------- last-finisher combine: 3rd block for batch b writes out[b] ----
    __threadfence();
    unsigned old = 0;
    if (lane == 0) old = atomicAdd(&g_cnt[b], 1u);
    old = __shfl_sync(0xffffffffu, old, 0);
    if (old == 2u){
        __threadfence();   // acquire: other blocks' writes now visible
        float dot = 0.f;
        if (lane < 24){
            float2 a = *(const float2*)&g_vec[0][b][2*lane];
            float2 g = *(const float2*)&g_vec[1][b][2*lane];
            dot = a.x*g.x + a.y*g.y;
        }
        #pragma unroll
        for (int o = 16; o; o >>= 1) dot += __shfl_xor_sync(0xffffffffu, dot, o);
        if (lane == 0){
            double logz = (double)(g_eac[0][b] + g_eac[1][b]) * M_LN2
                        + (double)__logf(dot);
            out[b] = (float)(logz - (double)g_gold[b]);
            g_cnt[b] = 0;   // reset for next graph replay
        }
    }
}

extern "C" void kernel_launch(void* const* d_in, const int* in_sizes, int n_in,
                              void* d_out, int out_size)
{
    const float* feats = (const float*)d_in[0];
    const float* masks = (const float*)d_in[1];
    const void*  tags  = (const void*) d_in[2];
    const float* trans = (const float*)d_in[3];
    float* out = (float*)d_out;
    dim3 grid(BB, 3);
    crf_scan_kernel<<<grid, 32>>>(feats, masks, tags, trans, out);
}

// round 13
// speedup vs baseline: 1.1129x; 1.1129x over previous
#include <cuda_runtime.h>
#include <math.h>

#define TT 48
#define SS 1024
#define HS 512
#define BB 256
#define TAG_START 45
#define TAG_STOP  46

typedef unsigned long long u64;

// scratch (device globals: allocation-free; zero-initialized at load)
__device__ float    g_vec[2][BB][64];   // [0]=alpha (fwd), [1]=gamma (bwd)
__device__ int      g_eac[2][BB];
__device__ float    g_gold[BB];
__device__ unsigned g_cnt[BB];          // last-finisher counters (reset after use)

// ---- packed f32x2 helpers ----
__device__ __forceinline__ u64 ffma2(u64 a, u64 b, u64 c){
    u64 d; asm("fma.rn.f32x2 %0, %1, %2, %3;" : "=l"(d) : "l"(a), "l"(b), "l"(c)); return d;
}
__device__ __forceinline__ u64 fadd2(u64 a, u64 b){
    u64 d; asm("add.rn.f32x2 %0, %1, %2;" : "=l"(d) : "l"(a), "l"(b)); return d;
}
__device__ __forceinline__ u64 pack2(float lo, float hi){
    u64 d; asm("mov.b64 %0, {%1, %2};" : "=l"(d) : "f"(lo), "f"(hi)); return d;
}
__device__ __forceinline__ void unpack2(u64 v, float& lo, float& hi){
    asm("mov.b64 {%0, %1}, %2;" : "=f"(lo), "=f"(hi) : "l"(v));
}
__device__ __forceinline__ float2 expf2(float2 f){
    return make_float2(__expf(f.x), __expf(f.y));
}
__device__ __forceinline__ float2 ldf2(const float* p, bool act){
    return act ? *(const float2*)p : make_float2(0.f, 0.f);
}

// matvec over smem vector, 8 accumulators (dep chain 6 deep instead of 12);
// produces s0,s1 and P0 (first 16B, reused for renorm)
#define MATVEC                                                                \
    const float* rp = &psh[pb][0];                                            \
    ulonglong2 P0 = *(const ulonglong2*)&rp[0];                               \
    u64 A0=0ull, A1=0ull, C0=0ull, C1=0ull;                                   \
    u64 D0=0ull, D1=0ull, F0=0ull, F1=0ull;                                   \
    _Pragma("unroll")                                                         \
    for (int q = 0; q < 6; q++){                                              \
        ulonglong2 P = (q == 0) ? P0 : *(const ulonglong2*)&rp[4*q];          \
        A0 = ffma2(W0[2*q],   P.x, A0);                                       \
        A1 = ffma2(W1[2*q],   P.x, A1);                                       \
        C0 = ffma2(W0[2*q+1], P.y, C0);                                       \
        C1 = ffma2(W1[2*q+1], P.y, C1);                                       \
    }                                                                         \
    _Pragma("unroll")                                                         \
    for (int q = 6; q < 12; q++){                                             \
        ulonglong2 P = *(const ulonglong2*)&rp[4*q];                          \
        D0 = ffma2(W0[2*q],   P.x, D0);                                       \
        D1 = ffma2(W1[2*q],   P.x, D1);                                       \
        F0 = ffma2(W0[2*q+1], P.y, F0);                                       \
        F1 = ffma2(W1[2*q+1], P.y, F1);                                       \
    }                                                                         \
    u64 S0 = fadd2(fadd2(A0, C0), fadd2(D0, F0));                             \
    u64 S1 = fadd2(fadd2(A1, C1), fadd2(D1, F1));                             \
    float l0, h0, l1, h1; unpack2(S0, l0, h0); unpack2(S1, l1, h1);           \
    float s0 = l0 + h0, s1 = l1 + h1;

// exact pow2 renorm factor from p[0] (exponent only, integer-exact)
#define RENORM                                                                \
    float p0lo, p0hi; unpack2(P0.x, p0lo, p0hi); (void)p0hi;                  \
    int e = ((__float_as_int(p0lo) >> 23) & 0xff) - 127;                      \
    e = max(-60, min(60, e));                                                 \
    float c = __int_as_float((127 - e) << 23);                                \
    eacc += e;

// forward steps: renormed / plain (pad lanes write zeros into psh[48..63])
#define FSTEP_R(EV, M) do { MATVEC RENORM                                     \
    float qx = s0 * ((EV).x * c), qy = s1 * ((EV).y * c);                     \
    vmy.x = ((M) > 0.5f) ? qx : vmy.x * c;                                    \
    vmy.y = ((M) > 0.5f) ? qy : vmy.y * c;                                    \
    *(float2*)&psh[pb ^ 1][j0] = vmy;                                         \
    pb ^= 1; __syncwarp();                                                    \
} while(0)

#define FSTEP_P(EV, M) do { MATVEC                                            \
    float qx = s0 * (EV).x, qy = s1 * (EV).y;                                 \
    vmy.x = ((M) > 0.5f) ? qx : vmy.x;                                        \
    vmy.y = ((M) > 0.5f) ? qy : vmy.y;                                        \
    *(float2*)&psh[pb ^ 1][j0] = vmy;                                         \
    pb ^= 1; __syncwarp();                                                    \
} while(0)

// backward steps: renormed / plain (store g*E_next for the following step)
#define BSTEP_R(EN, M) do { MATVEC RENORM                                     \
    float qx = s0 * c, qy = s1 * c;                                           \
    vmy.x = ((M) > 0.5f) ? qx : vmy.x * c;                                    \
    vmy.y = ((M) > 0.5f) ? qy : vmy.y * c;                                    \
    *(float2*)&psh[pb ^ 1][j0] = make_float2(vmy.x*(EN).x, vmy.y*(EN).y);     \
    pb ^= 1; __syncwarp();                                                    \
} while(0)

#define BSTEP_P(EN, M) do { MATVEC                                            \
    vmy.x = ((M) > 0.5f) ? s0 : vmy.x;                                        \
    vmy.y = ((M) > 0.5f) ? s1 : vmy.y;                                        \
    *(float2*)&psh[pb ^ 1][j0] = make_float2(vmy.x*(EN).x, vmy.y*(EN).y);     \
    pb ^= 1; __syncwarp();                                                    \
} while(0)

__global__ void __launch_bounds__(32) crf_scan_kernel(
    const float* __restrict__ feats,
    const float* __restrict__ masks,
    const void*  __restrict__ tagsp,
    const float* __restrict__ trans,
    float*       __restrict__ out)
{
    const int lane = threadIdx.x;
    const int b    = blockIdx.x;
    const int dir  = blockIdx.y;
    const int j0   = 2*lane;
    const bool act = (lane < 24);
    const float* fB = feats + (size_t)b * SS * TT;
    const float* mB = masks + (size_t)b * SS;

    if (dir == 2){
        // ---------------- gold-score block ----------------
        const int* t32 = (const int*)tagsp;
        int det = t32[1]|t32[3]|t32[5]|t32[7]|t32[9]|t32[11]|t32[13]|t32[15];
        const bool is64 = (det == 0);
        const long long* t64 = (const long long*)tagsp;

        float g = 0.f, lenf = 0.f;
        for (int si = lane; si < SS; si += 32){
            float m = mB[si];
            long long base = (long long)b * SS + si;
            int tg = is64 ? (int)t64[base] : t32[base];
            int pv = (si == 0) ? TAG_START : (is64 ? (int)t64[base-1] : t32[base-1]);
            g    += (fB[si*TT + tg] + trans[tg*TT + pv]) * m;
            lenf += m;
        }
        #pragma unroll
        for (int o = 16; o; o >>= 1){
            g    += __shfl_xor_sync(0xffffffffu, g,    o);
            lenf += __shfl_xor_sync(0xffffffffu, lenf, o);
        }
        if (lane == 0){
            int len = (int)lenf;
            int last = (len == 0) ? TAG_START
                                  : (is64 ? (int)t64[(long long)b*SS + len - 1]
                                          : t32[(long long)b*SS + len - 1]);
            g_gold[b] = g + trans[TAG_STOP*TT + last];
        }
    } else {
        // ---------------- scan block (dir 0 = fwd, 1 = bwd) ----------------
        __shared__ __align__(16) float psh[2][64];

        u64 W0[24], W1[24];
        #pragma unroll
        for (int kk = 0; kk < 24; kk++){
            float a0=0.f, a1=0.f, c0=0.f, c1=0.f;
            if (act){
                if (dir == 0){
                    float2 t0 = *(const float2*)&trans[j0*TT + 2*kk];
                    float2 t1 = *(const float2*)&trans[(j0+1)*TT + 2*kk];
                    a0 = __expf(t0.x); a1 = __expf(t0.y);
                    c0 = __expf(t1.x); c1 = __expf(t1.y);
                } else {
                    a0 = __expf(trans[(2*kk  )*TT + j0]);
                    a1 = __expf(trans[(2*kk+1)*TT + j0]);
                    c0 = __expf(trans[(2*kk  )*TT + j0+1]);
                    c1 = __expf(trans[(2*kk+1)*TT + j0+1]);
                }
            }
            W0[kk] = pack2(a0, a1);
            W1[kk] = pack2(c0, c1);
        }

        float2 vmy;
        int eacc = 0, pb = 0;
        if (dir == 0){
            vmy.x = (j0   == TAG_START) ? 1.f : 0.f;
            vmy.y = (j0+1 == TAG_START) ? 1.f : 0.f;
            *(float2*)&psh[0][j0] = vmy;
        } else {
            float w0 = act ? __expf(trans[TAG_STOP*TT + j0  ]) : 0.f;
            float w1 = act ? __expf(trans[TAG_STOP*TT + j0+1]) : 0.f;
            vmy = make_float2(w0, w1);
            float2 eL = expf2(ldf2(&fB[(size_t)1023*TT + j0], act));
            *(float2*)&psh[0][j0] = make_float2(w0*eL.x, w1*eL.y);
        }
        __syncwarp();

        // pipeline: raw loads 8 steps ahead, exp computed 4 steps ahead
        float2 e0[4], e1x[4], r1[4], r2[4];
        float4 m0, m1;

        if (dir == 0){
            #pragma unroll
            for (int u = 0; u < 4; u++){
                e0[u] = expf2(ldf2(&fB[(size_t)u*TT + j0], act));
                r1[u] = ldf2(&fB[(size_t)(4+u)*TT + j0], act);
            }
            m0 = *(const float4*)&mB[0];
            m1 = *(const float4*)&mB[4];

            for (int sb = 0; sb < HS; sb += 8){
                float4 m2 = *(const float4*)&mB[sb+8];
                #pragma unroll
                for (int u = 0; u < 4; u++){
                    r2[u]  = ldf2(&fB[(size_t)(sb+8+u)*TT + j0], act);
                    e1x[u] = expf2(r1[u]);
                }
                FSTEP_R(e0[0], m0.x); FSTEP_P(e0[1], m0.y);
                FSTEP_R(e0[2], m0.z); FSTEP_P(e0[3], m0.w);
                m0 = m2;

                float4 m1o = m1;
                m1 = *(const float4*)&mB[sb+12];
                #pragma unroll
                for (int u = 0; u < 4; u++){
                    r1[u] = ldf2(&fB[(size_t)(sb+12+u)*TT + j0], act);
                    e0[u] = expf2(r2[u]);
                }
                FSTEP_R(e1x[0], m1o.x); FSTEP_P(e1x[1], m1o.y);
                FSTEP_R(e1x[2], m1o.z); FSTEP_P(e1x[3], m1o.w);
            }
        } else {
            #pragma unroll
            for (int u = 0; u < 4; u++){
                e0[u] = expf2(ldf2(&fB[(size_t)(1022-u)*TT + j0], act));
                r1[u] = ldf2(&fB[(size_t)(1022-(4+u))*TT + j0], act);
            }
            m0 = *(const float4*)&mB[1020];   // reversed components
            m1 = *(const float4*)&mB[1016];

            for (int sb = 0; sb < HS; sb += 8){
                float4 m2 = *(const float4*)&mB[1020 - (sb+8)];
                #pragma unroll
                for (int u = 0; u < 4; u++){
                    r2[u]  = ldf2(&fB[(size_t)(1022-(sb+8+u))*TT + j0], act);
                    e1x[u] = expf2(r1[u]);
                }
                BSTEP_R(e0[0], m0.w); BSTEP_P(e0[1], m0.z);
                BSTEP_R(e0[2], m0.y); BSTEP_P(e0[3], m0.x);
                m0 = m2;

                float4 m1o = m1;
                m1 = *(const float4*)&mB[1020 - (sb+12)];
                #pragma unroll
                for (int u = 0; u < 4; u++){
                    r1[u] = ldf2(&fB[(size_t)(1022-(sb+12+u))*TT + j0], act);
                    e0[u] = expf2(r2[u]);
                }
                BSTEP_R(e1x[0], m1o.w); BSTEP_P(e1x[1], m1o.z);
                BSTEP_R(e1x[2], m1o.y); BSTEP_P(e1x[3], m1o.x);
            }
        }

        if (act){
            *(float2*)&g_vec[dir][b][j0] = vmy;
        } else {
            g_vec[dir][b][2*lane] = 0.f; g_vec[dir][b][2*lane+1] = 0.f;
        }
        if (lane == 0) g_eac[dir][b] = eacc;
    }

    // -------- last-finisher combine: 3rd block for batch b writes out[b] ----
    __threadfence();
    unsigned old = 0;
    if (lane == 0) old = atomicAdd(&g_cnt[b], 1u);
    old = __shfl_sync(0xffffffffu, old, 0);
    if (old == 2u){
        __threadfence();   // acquire: other blocks' writes now visible
        float dot = 0.f;
        if (lane < 24){
            float2 a = *(const float2*)&g_vec[0][b][2*lane];
            float2 g = *(const float2*)&g_vec[1][b][2*lane];
            dot = a.x*g.x + a.y*g.y;
        }
        #pragma unroll
        for (int o = 16; o; o >>= 1) dot += __shfl_xor_sync(0xffffffffu, dot, o);
        if (lane == 0){
            double logz = (double)(g_eac[0][b] + g_eac[1][b]) * M_LN2
                        + (double)__logf(dot);
            out[b] = (float)(logz - (double)g_gold[b]);
            g_cnt[b] = 0;   // reset for next graph replay
        }
    }
}

extern "C" void kernel_launch(void* const* d_in, const int* in_sizes, int n_in,
                              void* d_out, int out_size)
{
    const float* feats = (const float*)d_in[0];
    const float* masks = (const float*)d_in[1];
    const void*  tags  = (const void*) d_in[2];
    const float* trans = (const float*)d_in[3];
    float* out = (float*)d_out;
    dim3 grid(BB, 3);
    crf_scan_kernel<<<grid, 32>>>(feats, masks, tags, trans, out);
}

// round 16
// speedup vs baseline: 1.2526x; 1.1255x over previous
#include <cuda_runtime.h>
#include <math.h>

#define TT 48
#define SS 1024
#define HS 512
#define BB 256
#define TAG_START 45
#define TAG_STOP  46

typedef unsigned long long u64;

// scratch (device globals: allocation-free; zero-initialized at load)
__device__ float    g_vec[2][BB][64];   // [0]=alpha (fwd), [1]=gamma (bwd)
__device__ int      g_eac[2][BB];
__device__ float    g_gold[BB];
__device__ unsigned g_cnt[BB];          // last-finisher counters (reset after use)

// ---- packed f32x2 helpers ----
__device__ __forceinline__ u64 ffma2(u64 a, u64 b, u64 c){
    u64 d; asm("fma.rn.f32x2 %0, %1, %2, %3;" : "=l"(d) : "l"(a), "l"(b), "l"(c)); return d;
}
__device__ __forceinline__ u64 fadd2(u64 a, u64 b){
    u64 d; asm("add.rn.f32x2 %0, %1, %2;" : "=l"(d) : "l"(a), "l"(b)); return d;
}
__device__ __forceinline__ u64 pack2(float lo, float hi){
    u64 d; asm("mov.b64 %0, {%1, %2};" : "=l"(d) : "f"(lo), "f"(hi)); return d;
}
__device__ __forceinline__ void unpack2(u64 v, float& lo, float& hi){
    asm("mov.b64 {%0, %1}, %2;" : "=f"(lo), "=f"(hi) : "l"(v));
}
__device__ __forceinline__ float2 expf2(float2 f){
    return make_float2(__expf(f.x), __expf(f.y));
}
__device__ __forceinline__ float2 ldf2(const float* p, bool act){
    return act ? *(const float2*)p : make_float2(0.f, 0.f);
}
// volatile shared exchange (warp-synchronous: convergent loop, no syncwarp)
__device__ __forceinline__ ulonglong2 ldsv128(unsigned a){
    ulonglong2 r;
    asm volatile("ld.volatile.shared.v2.b64 {%0, %1}, [%2];"
                 : "=l"(r.x), "=l"(r.y) : "r"(a));
    return r;
}
__device__ __forceinline__ void stsv64(unsigned a, float2 v){
    asm volatile("st.volatile.shared.v2.f32 [%0], {%1, %2};"
                 :: "r"(a), "f"(v.x), "f"(v.y));
}

// matvec over smem vector (volatile LDS); produces s0,s1 and P0 (for renorm)
#define MATVEC                                                                \
    unsigned _ra = pbase + (unsigned)pb * 256u;                               \
    ulonglong2 P0 = ldsv128(_ra);                                             \
    u64 A0=0ull, A1=0ull, C0=0ull, C1=0ull;                                   \
    _Pragma("unroll")                                                         \
    for (int q = 0; q < 12; q++){                                             \
        ulonglong2 P = (q == 0) ? P0 : ldsv128(_ra + 16u*q);                  \
        A0 = ffma2(W0[2*q],   P.x, A0);                                       \
        A1 = ffma2(W1[2*q],   P.x, A1);                                       \
        C0 = ffma2(W0[2*q+1], P.y, C0);                                       \
        C1 = ffma2(W1[2*q+1], P.y, C1);                                       \
    }                                                                         \
    u64 S0 = fadd2(A0, C0), S1 = fadd2(A1, C1);                               \
    float l0, h0, l1, h1; unpack2(S0, l0, h0); unpack2(S1, l1, h1);           \
    float s0 = l0 + h0, s1 = l1 + h1;

// exact pow2 renorm factor from p[0] (exponent only, integer-exact)
#define RENORM                                                                \
    float p0lo, p0hi; unpack2(P0.x, p0lo, p0hi); (void)p0hi;                  \
    int e = ((__float_as_int(p0lo) >> 23) & 0xff) - 127;                      \
    e = max(-60, min(60, e));                                                 \
    float c = __int_as_float((127 - e) << 23);                                \
    eacc += e;

#define STORE_X(V)                                                            \
    stsv64(pbase + (unsigned)(pb ^ 1) * 256u + (unsigned)j0 * 4u, (V));       \
    pb ^= 1;

// forward steps: renormed / plain (pad lanes write zeros beyond float 47)
#define FSTEP_R(EV, M) do { MATVEC RENORM                                     \
    float qx = s0 * ((EV).x * c), qy = s1 * ((EV).y * c);                     \
    vmy.x = ((M) > 0.5f) ? qx : vmy.x * c;                                    \
    vmy.y = ((M) > 0.5f) ? qy : vmy.y * c;                                    \
    STORE_X(vmy)                                                              \
} while(0)

#define FSTEP_P(EV, M) do { MATVEC                                            \
    float qx = s0 * (EV).x, qy = s1 * (EV).y;                                 \
    vmy.x = ((M) > 0.5f) ? qx : vmy.x;                                        \
    vmy.y = ((M) > 0.5f) ? qy : vmy.y;                                        \
    STORE_X(vmy)                                                              \
} while(0)

// backward steps: renormed / plain (store g*E_next for the following step)
#define BSTEP_R(EN, M) do { MATVEC RENORM                                     \
    float qx = s0 * c, qy = s1 * c;                                           \
    vmy.x = ((M) > 0.5f) ? qx : vmy.x * c;                                    \
    vmy.y = ((M) > 0.5f) ? qy : vmy.y * c;                                    \
    STORE_X(make_float2(vmy.x*(EN).x, vmy.y*(EN).y))                          \
} while(0)

#define BSTEP_P(EN, M) do { MATVEC                                            \
    vmy.x = ((M) > 0.5f) ? s0 : vmy.x;                                        \
    vmy.y = ((M) > 0.5f) ? s1 : vmy.y;                                        \
    STORE_X(make_float2(vmy.x*(EN).x, vmy.y*(EN).y))                          \
} while(0)

__global__ void __launch_bounds__(32) crf_scan_kernel(
    const float* __restrict__ feats,
    const float* __restrict__ masks,
    const void*  __restrict__ tagsp,
    const float* __restrict__ trans,
    float*       __restrict__ out)
{
    const int lane = threadIdx.x;
    const int b    = blockIdx.x;
    const int dir  = blockIdx.y;
    const int j0   = 2*lane;
    const bool act = (lane < 24);
    const float* fB = feats + (size_t)b * SS * TT;
    const float* mB = masks + (size_t)b * SS;

    if (dir == 2){
        // ---------------- gold-score block ----------------
        const int* t32 = (const int*)tagsp;
        int det = t32[1]|t32[3]|t32[5]|t32[7]|t32[9]|t32[11]|t32[13]|t32[15];
        const bool is64 = (det == 0);
        const long long* t64 = (const long long*)tagsp;

        float g = 0.f, lenf = 0.f;
        for (int si = lane; si < SS; si += 32){
            float m = mB[si];
            long long base = (long long)b * SS + si;
            int tg = is64 ? (int)t64[base] : t32[base];
            int pv = (si == 0) ? TAG_START : (is64 ? (int)t64[base-1] : t32[base-1]);
            g    += (fB[si*TT + tg] + trans[tg*TT + pv]) * m;
            lenf += m;
        }
        #pragma unroll
        for (int o = 16; o; o >>= 1){
            g    += __shfl_xor_sync(0xffffffffu, g,    o);
            lenf += __shfl_xor_sync(0xffffffffu, lenf, o);
        }
        if (lane == 0){
            int len = (int)lenf;
            int last = (len == 0) ? TAG_START
                                  : (is64 ? (int)t64[(long long)b*SS + len - 1]
                                          : t32[(long long)b*SS + len - 1]);
            g_gold[b] = g + trans[TAG_STOP*TT + last];
        }
    } else {
        // ---------------- scan block (dir 0 = fwd, 1 = bwd) ----------------
        __shared__ __align__(16) float psh[2][64];
        const unsigned pbase = (unsigned)__cvta_generic_to_shared(&psh[0][0]);

        u64 W0[24], W1[24];
        #pragma unroll
        for (int kk = 0; kk < 24; kk++){
            float a0=0.f, a1=0.f, c0=0.f, c1=0.f;
            if (act){
                if (dir == 0){
                    float2 t0 = *(const float2*)&trans[j0*TT + 2*kk];
                    float2 t1 = *(const float2*)&trans[(j0+1)*TT + 2*kk];
                    a0 = __expf(t0.x); a1 = __expf(t0.y);
                    c0 = __expf(t1.x); c1 = __expf(t1.y);
                } else {
                    a0 = __expf(trans[(2*kk  )*TT + j0]);
                    a1 = __expf(trans[(2*kk+1)*TT + j0]);
                    c0 = __expf(trans[(2*kk  )*TT + j0+1]);
                    c1 = __expf(trans[(2*kk+1)*TT + j0+1]);
                }
            }
            W0[kk] = pack2(a0, a1);
            W1[kk] = pack2(c0, c1);
        }

        float2 vmy;
        int eacc = 0, pb = 0;
        if (dir == 0){
            vmy.x = (j0   == TAG_START) ? 1.f : 0.f;
            vmy.y = (j0+1 == TAG_START) ? 1.f : 0.f;
            stsv64(pbase + (unsigned)j0*4u, vmy);
        } else {
            float w0 = act ? __expf(trans[TAG_STOP*TT + j0  ]) : 0.f;
            float w1 = act ? __expf(trans[TAG_STOP*TT + j0+1]) : 0.f;
            vmy = make_float2(w0, w1);
            float2 eL = expf2(ldf2(&fB[(size_t)1023*TT + j0], act));
            stsv64(pbase + (unsigned)j0*4u, make_float2(w0*eL.x, w1*eL.y));
        }

        // pipeline: raw loads 8 steps ahead, exp computed 4 steps ahead
        float2 e0[4], e1x[4], r1[4], r2[4];
        float4 m0, m1;

        if (dir == 0){
            #pragma unroll
            for (int u = 0; u < 4; u++){
                e0[u] = expf2(ldf2(&fB[(size_t)u*TT + j0], act));
                r1[u] = ldf2(&fB[(size_t)(4+u)*TT + j0], act);
            }
            m0 = *(const float4*)&mB[0];
            m1 = *(const float4*)&mB[4];

            for (int sb = 0; sb < HS; sb += 8){
                float4 m2 = *(const float4*)&mB[sb+8];
                #pragma unroll
                for (int u = 0; u < 4; u++){
                    r2[u]  = ldf2(&fB[(size_t)(sb+8+u)*TT + j0], act);
                    e1x[u] = expf2(r1[u]);
                }
                FSTEP_R(e0[0], m0.x); FSTEP_P(e0[1], m0.y);
                FSTEP_R(e0[2], m0.z); FSTEP_P(e0[3], m0.w);
                m0 = m2;

                float4 m1o = m1;
                m1 = *(const float4*)&mB[sb+12];
                #pragma unroll
                for (int u = 0; u < 4; u++){
                    r1[u] = ldf2(&fB[(size_t)(sb+12+u)*TT + j0], act);
                    e0[u] = expf2(r2[u]);
                }
                FSTEP_R(e1x[0], m1o.x); FSTEP_P(e1x[1], m1o.y);
                FSTEP_R(e1x[2], m1o.z); FSTEP_P(e1x[3], m1o.w);
            }
        } else {
            #pragma unroll
            for (int u = 0; u < 4; u++){
                e0[u] = expf2(ldf2(&fB[(size_t)(1022-u)*TT + j0], act));
                r1[u] = ldf2(&fB[(size_t)(1022-(4+u))*TT + j0], act);
            }
            m0 = *(const float4*)&mB[1020];   // reversed components
            m1 = *(const float4*)&mB[1016];

            for (int sb = 0; sb < HS; sb += 8){
                float4 m2 = *(const float4*)&mB[1020 - (sb+8)];
                #pragma unroll
                for (int u = 0; u < 4; u++){
                    r2[u]  = ldf2(&fB[(size_t)(1022-(sb+8+u))*TT + j0], act);
                    e1x[u] = expf2(r1[u]);
                }
                BSTEP_R(e0[0], m0.w); BSTEP_P(e0[1], m0.z);
                BSTEP_R(e0[2], m0.y); BSTEP_P(e0[3], m0.x);
                m0 = m2;

                float4 m1o = m1;
                m1 = *(const float4*)&mB[1020 - (sb+12)];
                #pragma unroll
                for (int u = 0; u < 4; u++){
                    r1[u] = ldf2(&fB[(size_t)(1022-(sb+12+u))*TT + j0], act);
                    e0[u] = expf2(r2[u]);
                }
                BSTEP_R(e1x[0], m1o.w); BSTEP_P(e1x[1], m1o.z);
                BSTEP_R(e1x[2], m1o.y); BSTEP_P(e1x[3], m1o.x);
            }
        }

        if (act){
            *(float2*)&g_vec[dir][b][j0] = vmy;
        } else {
            g_vec[dir][b][2*lane] = 0.f; g_vec[dir][b][2*lane+1] = 0.f;
        }
        if (lane == 0) g_eac[dir][b] = eacc;
    }

    // -------- last-finisher combine: 3rd block for batch b writes out[b] ----
    __threadfence();
    unsigned old = 0;
    if (lane == 0) old = atomicAdd(&g_cnt[b], 1u);
    old = __shfl_sync(0xffffffffu, old, 0);
    if (old == 2u){
        __threadfence();   // acquire: other blocks' writes now visible
        float dot = 0.f;
        if (lane < 24){
            float2 a = *(const float2*)&g_vec[0][b][2*lane];
            float2 g = *(const float2*)&g_vec[1][b][2*lane];
            dot = a.x*g.x + a.y*g.y;
        }
        #pragma unroll
        for (int o = 16; o; o >>= 1) dot += __shfl_xor_sync(0xffffffffu, dot, o);
        if (lane == 0){
            double logz = (double)(g_eac[0][b] + g_eac[1][b]) * M_LN2
                        + (double)__logf(dot);
            out[b] = (float)(logz - (double)g_gold[b]);
            g_cnt[b] = 0;   // reset for next graph replay
        }
    }
}

extern "C" void kernel_launch(void* const* d_in, const int* in_sizes, int n_in,
                              void* d_out, int out_size)
{
    const float* feats = (const float*)d_in[0];
    const float* masks = (const float*)d_in[1];
    const void*  tags  = (const void*) d_in[2];
    const float* trans = (const float*)d_in[3];
    float* out = (float*)d_out;
    dim3 grid(BB, 3);
    crf_scan_kernel<<<grid, 32>>>(feats, masks, tags, trans, out);
}

// round 17
// speedup vs baseline: 1.6704x; 1.3336x over previous
#include <cuda_runtime.h>
#include <math.h>

#define TT 48
#define SS 1024
#define HS 512
#define BB 256
#define TAG_START 45
#define TAG_STOP  46

typedef unsigned long long u64;

// scratch (device globals: allocation-free; zero-initialized at load)
__device__ float    g_vec[2][BB][64];   // [0]=alpha (fwd), [1]=gamma (bwd)
__device__ int      g_eac[2][BB];
__device__ float    g_goldp[2][BB];     // partial gold sums per direction
__device__ float    g_lenp[2][BB];      // partial mask counts per direction
__device__ unsigned g_cnt[BB];          // last-finisher counters (reset after use)

// ---- packed f32x2 helpers ----
__device__ __forceinline__ u64 ffma2(u64 a, u64 b, u64 c){
    u64 d; asm("fma.rn.f32x2 %0, %1, %2, %3;" : "=l"(d) : "l"(a), "l"(b), "l"(c)); return d;
}
__device__ __forceinline__ u64 fadd2(u64 a, u64 b){
    u64 d; asm("add.rn.f32x2 %0, %1, %2;" : "=l"(d) : "l"(a), "l"(b)); return d;
}
__device__ __forceinline__ u64 pack2(float lo, float hi){
    u64 d; asm("mov.b64 %0, {%1, %2};" : "=l"(d) : "f"(lo), "f"(hi)); return d;
}
__device__ __forceinline__ void unpack2(u64 v, float& lo, float& hi){
    asm("mov.b64 {%0, %1}, %2;" : "=f"(lo), "=f"(hi) : "l"(v));
}
__device__ __forceinline__ float2 expf2(float2 f){
    return make_float2(__expf(f.x), __expf(f.y));
}
__device__ __forceinline__ float2 ldf2(const float* p, bool act){
    return act ? *(const float2*)p : make_float2(0.f, 0.f);
}
// volatile shared exchange (warp-synchronous: convergent loop, no syncwarp)
__device__ __forceinline__ ulonglong2 ldsv128(unsigned a){
    ulonglong2 r;
    asm volatile("ld.volatile.shared.v2.b64 {%0, %1}, [%2];"
                 : "=l"(r.x), "=l"(r.y) : "r"(a));
    return r;
}
__device__ __forceinline__ void stsv64(unsigned a, float2 v){
    asm volatile("st.volatile.shared.v2.f32 [%0], {%1, %2};"
                 :: "r"(a), "f"(v.x), "f"(v.y));
}

// matvec over smem vector (volatile LDS); produces s0,s1 and P0 (for renorm)
#define MATVEC                                                                \
    unsigned _ra = pbase + (unsigned)pb * 256u;                               \
    ulonglong2 P0 = ldsv128(_ra);                                             \
    u64 A0=0ull, A1=0ull, C0=0ull, C1=0ull;                                   \
    _Pragma("unroll")                                                         \
    for (int q = 0; q < 12; q++){                                             \
        ulonglong2 P = (q == 0) ? P0 : ldsv128(_ra + 16u*q);                  \
        A0 = ffma2(W0[2*q],   P.x, A0);                                       \
        A1 = ffma2(W1[2*q],   P.x, A1);                                       \
        C0 = ffma2(W0[2*q+1], P.y, C0);                                       \
        C1 = ffma2(W1[2*q+1], P.y, C1);                                       \
    }                                                                         \
    u64 S0 = fadd2(A0, C0), S1 = fadd2(A1, C1);                               \
    float l0, h0, l1, h1; unpack2(S0, l0, h0); unpack2(S1, l1, h1);           \
    float s0 = l0 + h0, s1 = l1 + h1;

// exact pow2 renorm factor from p[0] (exponent only, integer-exact)
#define RENORM                                                                \
    float p0lo, p0hi; unpack2(P0.x, p0lo, p0hi); (void)p0hi;                  \
    int e = ((__float_as_int(p0lo) >> 23) & 0xff) - 127;                      \
    e = max(-60, min(60, e));                                                 \
    float c = __int_as_float((127 - e) << 23);                                \
    eacc += e;

#define STORE_X(V)                                                            \
    stsv64(pbase + (unsigned)(pb ^ 1) * 256u + (unsigned)j0 * 4u, (V));       \
    pb ^= 1;

// forward steps: renormed / plain (pad lanes write zeros beyond float 47)
#define FSTEP_R(EV, M) do { MATVEC RENORM                                     \
    float qx = s0 * ((EV).x * c), qy = s1 * ((EV).y * c);                     \
    vmy.x = ((M) > 0.5f) ? qx : vmy.x * c;                                    \
    vmy.y = ((M) > 0.5f) ? qy : vmy.y * c;                                    \
    STORE_X(vmy)                                                              \
} while(0)

#define FSTEP_P(EV, M) do { MATVEC                                            \
    float qx = s0 * (EV).x, qy = s1 * (EV).y;                                 \
    vmy.x = ((M) > 0.5f) ? qx : vmy.x;                                        \
    vmy.y = ((M) > 0.5f) ? qy : vmy.y;                                        \
    STORE_X(vmy)                                                              \
} while(0)

// backward steps: renormed / plain (store g*E_next for the following step)
#define BSTEP_R(EN, M) do { MATVEC RENORM                                     \
    float qx = s0 * c, qy = s1 * c;                                           \
    vmy.x = ((M) > 0.5f) ? qx : vmy.x * c;                                    \
    vmy.y = ((M) > 0.5f) ? qy : vmy.y * c;                                    \
    STORE_X(make_float2(vmy.x*(EN).x, vmy.y*(EN).y))                          \
} while(0)

#define BSTEP_P(EN, M) do { MATVEC                                            \
    vmy.x = ((M) > 0.5f) ? s0 : vmy.x;                                        \
    vmy.y = ((M) > 0.5f) ? s1 : vmy.y;                                        \
    STORE_X(make_float2(vmy.x*(EN).x, vmy.y*(EN).y))                          \
} while(0)

__global__ void __launch_bounds__(32) crf_scan_kernel(
    const float* __restrict__ feats,
    const float* __restrict__ masks,
    const void*  __restrict__ tagsp,
    const float* __restrict__ trans,
    float*       __restrict__ out)
{
    const int lane = threadIdx.x;
    const int b    = blockIdx.x;
    const int dir  = blockIdx.y;      // 0 = fwd scan + gold[0:512), 1 = bwd scan + gold[512:1024)
    const int j0   = 2*lane;
    const bool act = (lane < 24);
    const float* fB = feats + (size_t)b * SS * TT;
    const float* mB = masks + (size_t)b * SS;

    {
        // ---------------- scan (dir 0 = fwd, 1 = bwd) ----------------
        __shared__ __align__(16) float psh[2][64];
        const unsigned pbase = (unsigned)__cvta_generic_to_shared(&psh[0][0]);

        u64 W0[24], W1[24];
        #pragma unroll
        for (int kk = 0; kk < 24; kk++){
            float a0=0.f, a1=0.f, c0=0.f, c1=0.f;
            if (act){
                if (dir == 0){
                    float2 t0 = *(const float2*)&trans[j0*TT + 2*kk];
                    float2 t1 = *(const float2*)&trans[(j0+1)*TT + 2*kk];
                    a0 = __expf(t0.x); a1 = __expf(t0.y);
                    c0 = __expf(t1.x); c1 = __expf(t1.y);
                } else {
                    a0 = __expf(trans[(2*kk  )*TT + j0]);
                    a1 = __expf(trans[(2*kk+1)*TT + j0]);
                    c0 = __expf(trans[(2*kk  )*TT + j0+1]);
                    c1 = __expf(trans[(2*kk+1)*TT + j0+1]);
                }
            }
            W0[kk] = pack2(a0, a1);
            W1[kk] = pack2(c0, c1);
        }

        float2 vmy;
        int eacc = 0, pb = 0;
        if (dir == 0){
            vmy.x = (j0   == TAG_START) ? 1.f : 0.f;
            vmy.y = (j0+1 == TAG_START) ? 1.f : 0.f;
            stsv64(pbase + (unsigned)j0*4u, vmy);
        } else {
            float w0 = act ? __expf(trans[TAG_STOP*TT + j0  ]) : 0.f;
            float w1 = act ? __expf(trans[TAG_STOP*TT + j0+1]) : 0.f;
            vmy = make_float2(w0, w1);
            float2 eL = expf2(ldf2(&fB[(size_t)1023*TT + j0], act));
            stsv64(pbase + (unsigned)j0*4u, make_float2(w0*eL.x, w1*eL.y));
        }

        // pipeline: raw loads 8 steps ahead, exp computed 4 steps ahead
        float2 e0[4], e1x[4], r1[4], r2[4];
        float4 m0, m1;

        if (dir == 0){
            #pragma unroll
            for (int u = 0; u < 4; u++){
                e0[u] = expf2(ldf2(&fB[(size_t)u*TT + j0], act));
                r1[u] = ldf2(&fB[(size_t)(4+u)*TT + j0], act);
            }
            m0 = *(const float4*)&mB[0];
            m1 = *(const float4*)&mB[4];

            for (int sb = 0; sb < HS; sb += 8){
                float4 m2 = *(const float4*)&mB[sb+8];
                #pragma unroll
                for (int u = 0; u < 4; u++){
                    r2[u]  = ldf2(&fB[(size_t)(sb+8+u)*TT + j0], act);
                    e1x[u] = expf2(r1[u]);
                }
                FSTEP_R(e0[0], m0.x); FSTEP_P(e0[1], m0.y);
                FSTEP_R(e0[2], m0.z); FSTEP_P(e0[3], m0.w);
                m0 = m2;

                float4 m1o = m1;
                m1 = *(const float4*)&mB[sb+12];
                #pragma unroll
                for (int u = 0; u < 4; u++){
                    r1[u] = ldf2(&fB[(size_t)(sb+12+u)*TT + j0], act);
                    e0[u] = expf2(r2[u]);
                }
                FSTEP_R(e1x[0], m1o.x); FSTEP_P(e1x[1], m1o.y);
                FSTEP_R(e1x[2], m1o.z); FSTEP_P(e1x[3], m1o.w);
            }
        } else {
            #pragma unroll
            for (int u = 0; u < 4; u++){
                e0[u] = expf2(ldf2(&fB[(size_t)(1022-u)*TT + j0], act));
                r1[u] = ldf2(&fB[(size_t)(1022-(4+u))*TT + j0], act);
            }
            m0 = *(const float4*)&mB[1020];   // reversed components
            m1 = *(const float4*)&mB[1016];

            for (int sb = 0; sb < HS; sb += 8){
                float4 m2 = *(const float4*)&mB[1020 - (sb+8)];
                #pragma unroll
                for (int u = 0; u < 4; u++){
                    r2[u]  = ldf2(&fB[(size_t)(1022-(sb+8+u))*TT + j0], act);
                    e1x[u] = expf2(r1[u]);
                }
                BSTEP_R(e0[0], m0.w); BSTEP_P(e0[1], m0.z);
                BSTEP_R(e0[2], m0.y); BSTEP_P(e0[3], m0.x);
                m0 = m2;

                float4 m1o = m1;
                m1 = *(const float4*)&mB[1020 - (sb+12)];
                #pragma unroll
                for (int u = 0; u < 4; u++){
                    r1[u] = ldf2(&fB[(size_t)(1022-(sb+12+u))*TT + j0], act);
                    e0[u] = expf2(r2[u]);
                }
                BSTEP_R(e1x[0], m1o.w); BSTEP_P(e1x[1], m1o.z);
                BSTEP_R(e1x[2], m1o.y); BSTEP_P(e1x[3], m1o.x);
            }
        }

        if (act){
            *(float2*)&g_vec[dir][b][j0] = vmy;
        } else {
            g_vec[dir][b][2*lane] = 0.f; g_vec[dir][b][2*lane+1] = 0.f;
        }
        if (lane == 0) g_eac[dir][b] = eacc;
    }

    // -------- gold-score half: si in [dir*HS, dir*HS + HS) --------
    {
        const int* t32 = (const int*)tagsp;
        int det = t32[1]|t32[3]|t32[5]|t32[7]|t32[9]|t32[11]|t32[13]|t32[15];
        const bool is64 = (det == 0);
        const long long* t64 = (const long long*)tagsp;

        float g = 0.f, lenf = 0.f;
        const int si0 = dir * HS;
        for (int ii = 0; ii < HS; ii += 32){
            int si = si0 + ii + lane;
            float m = mB[si];
            long long base = (long long)b * SS + si;
            int tg = is64 ? (int)t64[base] : t32[base];
            int pv = (si == 0) ? TAG_START : (is64 ? (int)t64[base-1] : t32[base-1]);
            g    += (fB[si*TT + tg] + trans[tg*TT + pv]) * m;
            lenf += m;
        }
        #pragma unroll
        for (int o = 16; o; o >>= 1){
            g    += __shfl_xor_sync(0xffffffffu, g,    o);
            lenf += __shfl_xor_sync(0xffffffffu, lenf, o);
        }
        if (lane == 0){ g_goldp[dir][b] = g; g_lenp[dir][b] = lenf; }
    }

    // -------- last-finisher combine: 2nd block for batch b writes out[b] ----
    __threadfence();
    unsigned old = 0;
    if (lane == 0) old = atomicAdd(&g_cnt[b], 1u);
    old = __shfl_sync(0xffffffffu, old, 0);
    if (old == 1u){
        __threadfence();   // acquire: other block's writes now visible
        float dot = 0.f;
        if (lane < 24){
            float2 a = *(const float2*)&g_vec[0][b][2*lane];
            float2 g = *(const float2*)&g_vec[1][b][2*lane];
            dot = a.x*g.x + a.y*g.y;
        }
        #pragma unroll
        for (int o = 16; o; o >>= 1) dot += __shfl_xor_sync(0xffffffffu, dot, o);
        if (lane == 0){
            const int* t32 = (const int*)tagsp;
            int det = t32[1]|t32[3]|t32[5]|t32[7]|t32[9]|t32[11]|t32[13]|t32[15];
            const bool is64 = (det == 0);
            const long long* t64 = (const long long*)tagsp;

            float gtot = g_goldp[0][b] + g_goldp[1][b];
            int   len  = (int)(g_lenp[0][b] + g_lenp[1][b]);
            int last = (len == 0) ? TAG_START
                                  : (is64 ? (int)t64[(long long)b*SS + len - 1]
                                          : t32[(long long)b*SS + len - 1]);
            gtot += trans[TAG_STOP*TT + last];

            double logz = (double)(g_eac[0][b] + g_eac[1][b]) * M_LN2
                        + (double)__logf(dot);
            out[b] = (float)(logz - (double)gtot);
            g_cnt[b] = 0;   // reset for next graph replay
        }
    }
}

extern "C" void kernel_launch(void* const* d_in, const int* in_sizes, int n_in,
                              void* d_out, int out_size)
{
    const float* feats = (const float*)d_in[0];
    const float* masks = (const float*)d_in[1];
    const void*  tags  = (const void*) d_in[2];
    const float* trans = (const float*)d_in[3];
    float* out = (float*)d_out;
    dim3 grid(BB, 2);
    crf_scan_kernel<<<grid, 32>>>(feats, masks, tags, trans, out);
}